// round 15
// baseline (speedup 1.0000x reference)
#include <cuda_runtime.h>
#include <math.h>

// LIANetLight hash-grid encoder.
// Inputs (metadata order):
//  0: x0      float32 [B]
//  1: y0      float32 [B]
//  2: tables  float32 [T, 2]
//  3: seeds   uint32  [L]
//  4: level_N float32 [L]
//  5: memorized_crop_size (scalar)
//  6: complete_tile_size  (scalar)
// Output: float32 [B, L*2, H, W]

#define HASH_P1 2654435761u
#define HASH_P2 805459861u
// levels >= this index gather L2-only (working set >> L1); below: L1-cached
#define L1_LEVELS 10

__device__ __forceinline__ float read_scalar_as_float(const int* p) {
    int v = *p;
    if (v > 0 && v < (1 << 24)) return (float)v;
    return __int_as_float(v);
}

__device__ __forceinline__ void store_cs(float* p, float v) {
    asm volatile("st.global.cs.f32 [%0], %1;" :: "l"(p), "f"(v) : "memory");
}

// L1-cached non-coherent gather (coarse/mid levels: working set fits L1).
__device__ __forceinline__ float2 ldg_l1(const float2* p) {
    float2 v;
    asm volatile("ld.global.nc.v2.f32 {%0, %1}, [%2];"
                 : "=f"(v.x), "=f"(v.y) : "l"(p));
    return v;
}

// L2-only gather (fine levels: working set thrashes L1 -> skip L1 fill/evict).
__device__ __forceinline__ float2 ldg_l2(const float2* p) {
    float2 v;
    asm volatile("ld.global.cg.v2.f32 {%0, %1}, [%2];"
                 : "=f"(v.x), "=f"(v.y) : "l"(p));
    return v;
}

// ---------------------------------------------------------------------------
// Direct kernel, 1 pixel/thread, 128-thread CTAs, grid=(HW/128, B).
// Structure identical to the fastest measured variant; per-level cache-tier
// split: levels < L1_LEVELS gather via L1, levels >= L1_LEVELS gather L2-only
// (no L1 fill/eviction work, no pollution of the coarse levels' L1 lines).
// Requires: T power of two, L == 16, HW % 128 == 0.
// ---------------------------------------------------------------------------
__global__ void __launch_bounds__(128)
hashenc_fast(const float* __restrict__ x0,
             const float* __restrict__ y0,
             const float2* __restrict__ tables,
             const unsigned int* __restrict__ seeds,
             const float* __restrict__ levelN,
             const int* __restrict__ tile_ptr,
             float* __restrict__ out,
             int H, unsigned int mask)
{
    const int L = 16;

    __shared__ float s_scale[16];
    __shared__ unsigned int s_seed[16];
    if (threadIdx.x < L) {
        const float tf = read_scalar_as_float(tile_ptr);
        s_scale[threadIdx.x] = levelN[threadIdx.x] / tf;
        s_seed[threadIdx.x]  = seeds[threadIdx.x];
    }
    __syncthreads();

    const int HW  = H * H;
    const int b   = blockIdx.y;
    const int pix = (int)(blockIdx.x * 128u + threadIdx.x);   // < HW by grid
    const int w   = pix % H;     // H==256 -> AND
    const int h   = pix / H;     // -> SHR

    const float px = (float)w + __ldg(&x0[b]);
    const float py = (float)h + __ldg(&y0[b]);

    float* outb = out + (size_t)b * (size_t)(2 * L) * (size_t)HW + pix;

    #pragma unroll
    for (int l = 0; l < L; l++) {
        const float sc        = s_scale[l];
        const unsigned int se = s_seed[l];

        const float xn  = px * sc;
        const float fxf = floorf(xn);
        const float fx  = xn - fxf;
        const float yn  = py * sc;
        const float fyf = floorf(yn);
        const float fy  = yn - fyf;

        const unsigned int hx0 = (unsigned int)(int)fxf * HASH_P1;
        const unsigned int hx1 = hx0 + HASH_P1;        // (ix0+1)*P1 mod 2^32
        unsigned int hy0 = (unsigned int)(int)fyf * HASH_P2;
        unsigned int hy1 = hy0 + HASH_P2;              // (iy0+1)*P2 mod 2^32
        hy0 ^= se;                                     // fold seed AFTER the adds
        hy1 ^= se;

        float2 f00, f10, f01, f11;
        if (l < L1_LEVELS) {   // compile-time in the unrolled loop
            f00 = ldg_l1(&tables[(hx0 ^ hy0) & mask]);
            f10 = ldg_l1(&tables[(hx1 ^ hy0) & mask]);
            f01 = ldg_l1(&tables[(hx0 ^ hy1) & mask]);
            f11 = ldg_l1(&tables[(hx1 ^ hy1) & mask]);
        } else {
            f00 = ldg_l2(&tables[(hx0 ^ hy0) & mask]);
            f10 = ldg_l2(&tables[(hx1 ^ hy0) & mask]);
            f01 = ldg_l2(&tables[(hx0 ^ hy1) & mask]);
            f11 = ldg_l2(&tables[(hx1 ^ hy1) & mask]);
        }

        const float gx = 1.0f - fx;
        const float gy = 1.0f - fy;
        const float w00 = gx * gy, w10 = fx * gy;
        const float w01 = gx * fy, w11 = fx * fy;

        const float ex = w00 * f00.x + w10 * f10.x + w01 * f01.x + w11 * f11.x;
        const float ey = w00 * f00.y + w10 * f10.y + w01 * f01.y + w11 * f11.y;

        store_cs(outb + (size_t)(2 * l)     * (size_t)HW, ex);
        store_cs(outb + (size_t)(2 * l + 1) * (size_t)HW, ey);
    }
}

// ---------------------------------------------------------------------------
// Generic fallback: one thread per pixel, runtime L / non-pow2 T.
// ---------------------------------------------------------------------------
template <int LFIX, bool POW2>
__global__ void __launch_bounds__(256)
hashenc_kernel(const float* __restrict__ x0,
               const float* __restrict__ y0,
               const float2* __restrict__ tables,
               const unsigned int* __restrict__ seeds,
               const float* __restrict__ levelN,
               const int* __restrict__ tile_ptr,
               float* __restrict__ out,
               int B, int H, int Lrt,
               unsigned int T, unsigned int mask)
{
    const int L = (LFIX > 0) ? LFIX : Lrt;

    __shared__ float s_scale[64];
    __shared__ unsigned int s_seed[64];
    if (threadIdx.x < L) {
        float tf = read_scalar_as_float(tile_ptr);
        s_scale[threadIdx.x] = levelN[threadIdx.x] / tf;
        s_seed[threadIdx.x]  = seeds[threadIdx.x];
    }
    __syncthreads();

    const int HW = H * H;
    const long long total = (long long)B * HW;
    const long long tid = (long long)blockIdx.x * blockDim.x + threadIdx.x;
    if (tid >= total) return;

    const int pix = (int)(tid % HW);
    const int b   = (int)(tid / HW);
    const int w   = pix % H;
    const int h   = pix / H;

    const float px = (float)w + x0[b];
    const float py = (float)h + y0[b];

    float* outb = out + (size_t)b * (size_t)(2 * L) * (size_t)HW + pix;

    #pragma unroll
    for (int l = 0; l < L; l++) {
        const float sc = s_scale[l];
        const float xn = px * sc;
        const float yn = py * sc;
        const float fx0f = floorf(xn);
        const float fy0f = floorf(yn);
        const int ix0 = (int)fx0f;
        const int iy0 = (int)fy0f;
        const float fx = xn - fx0f;
        const float fy = yn - fy0f;

        const unsigned int se  = s_seed[l];
        const unsigned int hx0 = (unsigned int)ix0 * HASH_P1;
        const unsigned int hx1 = hx0 + HASH_P1;
        const unsigned int hy0 = (unsigned int)iy0 * HASH_P2;
        const unsigned int hy1 = hy0 + HASH_P2;

        unsigned int i00, i10, i01, i11;
        if (POW2) {
            i00 = (hx0 ^ hy0 ^ se) & mask;
            i10 = (hx1 ^ hy0 ^ se) & mask;
            i01 = (hx0 ^ hy1 ^ se) & mask;
            i11 = (hx1 ^ hy1 ^ se) & mask;
        } else {
            i00 = (hx0 ^ hy0 ^ se) % T;
            i10 = (hx1 ^ hy0 ^ se) % T;
            i01 = (hx0 ^ hy1 ^ se) % T;
            i11 = (hx1 ^ hy1 ^ se) % T;
        }

        const float2 f00 = __ldg(&tables[i00]);
        const float2 f10 = __ldg(&tables[i10]);
        const float2 f01 = __ldg(&tables[i01]);
        const float2 f11 = __ldg(&tables[i11]);

        const float gx = 1.0f - fx;
        const float gy = 1.0f - fy;
        const float w00 = gx * gy;
        const float w10 = fx * gy;
        const float w01 = gx * fy;
        const float w11 = fx * fy;

        const float ex = w00 * f00.x + w10 * f10.x + w01 * f01.x + w11 * f11.x;
        const float ey = w00 * f00.y + w10 * f10.y + w01 * f01.y + w11 * f11.y;

        outb[(size_t)(2 * l)     * (size_t)HW] = ex;
        outb[(size_t)(2 * l + 1) * (size_t)HW] = ey;
    }
}

extern "C" void kernel_launch(void* const* d_in, const int* in_sizes, int n_in,
                              void* d_out, int out_size)
{
    const float*        x0     = (const float*)d_in[0];
    const float*        y0     = (const float*)d_in[1];
    const float2*       tables = (const float2*)d_in[2];
    const unsigned int* seeds  = (const unsigned int*)d_in[3];
    const float*        levelN = (const float*)d_in[4];
    const int*          tile   = (const int*)d_in[6];   // complete_tile_size scalar
    float*              out    = (float*)d_out;

    const int B = in_sizes[0];
    const int L = in_sizes[3];
    const unsigned int T = (unsigned int)(in_sizes[2] / 2);   // FEAT_DIM = 2

    const long long hw = (long long)out_size / ((long long)B * 2LL * (long long)L);
    int H = (int)(sqrt((double)hw) + 0.5);

    const bool pow2 = (T & (T - 1)) == 0;
    const unsigned int mask = T - 1;
    const int HW = H * H;

    if (pow2 && L == 16 && (HW % 128) == 0 && B <= 65535) {
        dim3 grid(HW / 128, B);
        hashenc_fast<<<grid, 128>>>(x0, y0, tables, seeds, levelN, tile,
                                    out, H, mask);
        return;
    }

    const long long total = (long long)B * HW;
    const int threads = 256;
    const int blocks = (int)((total + threads - 1) / threads);

    if (L == 16) {
        if (pow2)
            hashenc_kernel<16, true><<<blocks, threads>>>(x0, y0, tables, seeds, levelN,
                                                          tile, out, B, H, L, T, mask);
        else
            hashenc_kernel<16, false><<<blocks, threads>>>(x0, y0, tables, seeds, levelN,
                                                           tile, out, B, H, L, T, mask);
    } else {
        if (pow2)
            hashenc_kernel<0, true><<<blocks, threads>>>(x0, y0, tables, seeds, levelN,
                                                         tile, out, B, H, L, T, mask);
        else
            hashenc_kernel<0, false><<<blocks, threads>>>(x0, y0, tables, seeds, levelN,
                                                          tile, out, B, H, L, T, mask);
    }
}

// round 16
// speedup vs baseline: 1.1673x; 1.1673x over previous
#include <cuda_runtime.h>
#include <math.h>

// LIANetLight hash-grid encoder.
// Inputs (metadata order):
//  0: x0      float32 [B]
//  1: y0      float32 [B]
//  2: tables  float32 [T, 2]
//  3: seeds   uint32  [L]
//  4: level_N float32 [L]
//  5: memorized_crop_size (scalar)
//  6: complete_tile_size  (scalar)
// Output: float32 [B, L*2, H, W]

#define HASH_P1 2654435761u
#define HASH_P2 805459861u

__device__ __forceinline__ float read_scalar_as_float(const int* p) {
    int v = *p;
    if (v > 0 && v < (1 << 24)) return (float)v;
    return __int_as_float(v);
}

__device__ __forceinline__ void store_cs(float* p, float v) {
    asm volatile("st.global.cs.f32 [%0], %1;" :: "l"(p), "f"(v) : "memory");
}

// ---------------------------------------------------------------------------
// Vertical-pair kernel: each thread handles pixels (2h', w) and (2h'+1, w).
// For levels with scale <= 1 the two pixels span at most 3 distinct cell
// rows (floor monotonicity), so 6 gathers cover both pixels' 8 corners:
// rows iy1, iy1+1, iy2+1; pixel2's bottom row is a register select between
// the first two (iy2 == iy1 ?). The branch is uniform per level (depends
// only on s_scale[l]). Levels with scale > 1 use the plain 8-gather path.
// Warp = 32 consecutive w -> all stores coalesced. No barriers.
// Requires: T power of two, L == 16, H even, H*H/2 % 128 == 0.
// ---------------------------------------------------------------------------
__global__ void __launch_bounds__(128)
hashenc_vp(const float* __restrict__ x0,
           const float* __restrict__ y0,
           const float2* __restrict__ tables,
           const unsigned int* __restrict__ seeds,
           const float* __restrict__ levelN,
           const int* __restrict__ tile_ptr,
           float* __restrict__ out,
           int H, unsigned int mask)
{
    const int L = 16;

    __shared__ float s_scale[16];
    __shared__ unsigned int s_seed[16];
    if (threadIdx.x < L) {
        const float tf = read_scalar_as_float(tile_ptr);
        s_scale[threadIdx.x] = levelN[threadIdx.x] / tf;
        s_seed[threadIdx.x]  = seeds[threadIdx.x];
    }
    __syncthreads();

    const int HW   = H * H;
    const int b    = blockIdx.y;
    const int idx  = (int)(blockIdx.x * 128u + threadIdx.x);  // < H/2*H by grid
    const int hh   = idx / H;          // 0..H/2-1
    const int w    = idx - hh * H;     // 0..H-1
    const int h1   = 2 * hh;

    const float ox = __ldg(&x0[b]);
    const float oy = __ldg(&y0[b]);
    const float px  = (float)w + ox;
    const float py1 = (float)h1 + oy;
    const float py2 = py1 + 1.0f;

    float* outb = out + (size_t)b * (size_t)(2 * L) * (size_t)HW
                      + (size_t)h1 * (size_t)H + w;     // pixel1; pixel2 = +H

    #pragma unroll
    for (int l = 0; l < L; l++) {
        const float sc        = s_scale[l];
        const unsigned int se = s_seed[l];

        // shared x-chain
        const float xn  = px * sc;
        const float fxf = floorf(xn);
        const float fx  = xn - fxf;
        const float gx  = 1.0f - fx;
        const unsigned int hx0 = (unsigned int)(int)fxf * HASH_P1;
        const unsigned int hx1 = hx0 + HASH_P1;

        // y-chains for both pixels
        const float yn1  = py1 * sc;
        const float fyf1 = floorf(yn1);
        const float fy1  = yn1 - fyf1;
        const int iy1    = (int)fyf1;
        const float yn2  = py2 * sc;
        const float fyf2 = floorf(yn2);
        const float fy2  = yn2 - fyf2;
        const int iy2    = (int)fyf2;

        float2 p1_00, p1_10, p1_01, p1_11;   // pixel1 corners
        float2 p2_00, p2_10, p2_01, p2_11;   // pixel2 corners

        if (sc <= 1.0f) {   // uniform branch: iy2 <= iy1+1 guaranteed
            unsigned int hyA = (unsigned int)iy1 * HASH_P2;        // row iy1
            unsigned int hyB = hyA + HASH_P2;                      // row iy1+1
            unsigned int hyC = (unsigned int)iy2 * HASH_P2 + HASH_P2; // row iy2+1
            hyA ^= se; hyB ^= se; hyC ^= se;

            const float2 A0 = __ldg(&tables[(hx0 ^ hyA) & mask]);
            const float2 A1 = __ldg(&tables[(hx1 ^ hyA) & mask]);
            const float2 B0 = __ldg(&tables[(hx0 ^ hyB) & mask]);
            const float2 B1 = __ldg(&tables[(hx1 ^ hyB) & mask]);
            const float2 C0 = __ldg(&tables[(hx0 ^ hyC) & mask]);
            const float2 C1 = __ldg(&tables[(hx1 ^ hyC) & mask]);

            p1_00 = A0; p1_10 = A1; p1_01 = B0; p1_11 = B1;
            const bool same = (iy2 == iy1);
            p2_00 = same ? A0 : B0;
            p2_10 = same ? A1 : B1;
            p2_01 = C0; p2_11 = C1;
        } else {            // fine levels: independent 8 gathers
            unsigned int hyA = (unsigned int)iy1 * HASH_P2;
            unsigned int hyB = hyA + HASH_P2;
            unsigned int hyC = (unsigned int)iy2 * HASH_P2;
            unsigned int hyD = hyC + HASH_P2;
            hyA ^= se; hyB ^= se; hyC ^= se; hyD ^= se;

            p1_00 = __ldg(&tables[(hx0 ^ hyA) & mask]);
            p1_10 = __ldg(&tables[(hx1 ^ hyA) & mask]);
            p1_01 = __ldg(&tables[(hx0 ^ hyB) & mask]);
            p1_11 = __ldg(&tables[(hx1 ^ hyB) & mask]);
            p2_00 = __ldg(&tables[(hx0 ^ hyC) & mask]);
            p2_10 = __ldg(&tables[(hx1 ^ hyC) & mask]);
            p2_01 = __ldg(&tables[(hx0 ^ hyD) & mask]);
            p2_11 = __ldg(&tables[(hx1 ^ hyD) & mask]);
        }

        // pixel1 interpolation
        {
            const float gy = 1.0f - fy1;
            const float w00 = gx * gy,  w10 = fx * gy;
            const float w01 = gx * fy1, w11 = fx * fy1;
            const float ex = w00 * p1_00.x + w10 * p1_10.x + w01 * p1_01.x + w11 * p1_11.x;
            const float ey = w00 * p1_00.y + w10 * p1_10.y + w01 * p1_01.y + w11 * p1_11.y;
            store_cs(outb + (size_t)(2 * l)     * (size_t)HW, ex);
            store_cs(outb + (size_t)(2 * l + 1) * (size_t)HW, ey);
        }
        // pixel2 interpolation
        {
            const float gy = 1.0f - fy2;
            const float w00 = gx * gy,  w10 = fx * gy;
            const float w01 = gx * fy2, w11 = fx * fy2;
            const float ex = w00 * p2_00.x + w10 * p2_10.x + w01 * p2_01.x + w11 * p2_11.x;
            const float ey = w00 * p2_00.y + w10 * p2_10.y + w01 * p2_01.y + w11 * p2_11.y;
            store_cs(outb + (size_t)(2 * l)     * (size_t)HW + H, ex);
            store_cs(outb + (size_t)(2 * l + 1) * (size_t)HW + H, ey);
        }
    }
}

// ---------------------------------------------------------------------------
// Generic fallback: one thread per pixel, runtime L / non-pow2 T.
// ---------------------------------------------------------------------------
template <int LFIX, bool POW2>
__global__ void __launch_bounds__(256)
hashenc_kernel(const float* __restrict__ x0,
               const float* __restrict__ y0,
               const float2* __restrict__ tables,
               const unsigned int* __restrict__ seeds,
               const float* __restrict__ levelN,
               const int* __restrict__ tile_ptr,
               float* __restrict__ out,
               int B, int H, int Lrt,
               unsigned int T, unsigned int mask)
{
    const int L = (LFIX > 0) ? LFIX : Lrt;

    __shared__ float s_scale[64];
    __shared__ unsigned int s_seed[64];
    if (threadIdx.x < L) {
        float tf = read_scalar_as_float(tile_ptr);
        s_scale[threadIdx.x] = levelN[threadIdx.x] / tf;
        s_seed[threadIdx.x]  = seeds[threadIdx.x];
    }
    __syncthreads();

    const int HW = H * H;
    const long long total = (long long)B * HW;
    const long long tid = (long long)blockIdx.x * blockDim.x + threadIdx.x;
    if (tid >= total) return;

    const int pix = (int)(tid % HW);
    const int b   = (int)(tid / HW);
    const int w   = pix % H;
    const int h   = pix / H;

    const float px = (float)w + x0[b];
    const float py = (float)h + y0[b];

    float* outb = out + (size_t)b * (size_t)(2 * L) * (size_t)HW + pix;

    #pragma unroll
    for (int l = 0; l < L; l++) {
        const float sc = s_scale[l];
        const float xn = px * sc;
        const float yn = py * sc;
        const float fx0f = floorf(xn);
        const float fy0f = floorf(yn);
        const int ix0 = (int)fx0f;
        const int iy0 = (int)fy0f;
        const float fx = xn - fx0f;
        const float fy = yn - fy0f;

        const unsigned int se  = s_seed[l];
        const unsigned int hx0 = (unsigned int)ix0 * HASH_P1;
        const unsigned int hx1 = hx0 + HASH_P1;
        const unsigned int hy0 = (unsigned int)iy0 * HASH_P2;
        const unsigned int hy1 = hy0 + HASH_P2;

        unsigned int i00, i10, i01, i11;
        if (POW2) {
            i00 = (hx0 ^ hy0 ^ se) & mask;
            i10 = (hx1 ^ hy0 ^ se) & mask;
            i01 = (hx0 ^ hy1 ^ se) & mask;
            i11 = (hx1 ^ hy1 ^ se) & mask;
        } else {
            i00 = (hx0 ^ hy0 ^ se) % T;
            i10 = (hx1 ^ hy0 ^ se) % T;
            i01 = (hx0 ^ hy1 ^ se) % T;
            i11 = (hx1 ^ hy1 ^ se) % T;
        }

        const float2 f00 = __ldg(&tables[i00]);
        const float2 f10 = __ldg(&tables[i10]);
        const float2 f01 = __ldg(&tables[i01]);
        const float2 f11 = __ldg(&tables[i11]);

        const float gx = 1.0f - fx;
        const float gy = 1.0f - fy;
        const float w00 = gx * gy;
        const float w10 = fx * gy;
        const float w01 = gx * fy;
        const float w11 = fx * fy;

        const float ex = w00 * f00.x + w10 * f10.x + w01 * f01.x + w11 * f11.x;
        const float ey = w00 * f00.y + w10 * f10.y + w01 * f01.y + w11 * f11.y;

        outb[(size_t)(2 * l)     * (size_t)HW] = ex;
        outb[(size_t)(2 * l + 1) * (size_t)HW] = ey;
    }
}

extern "C" void kernel_launch(void* const* d_in, const int* in_sizes, int n_in,
                              void* d_out, int out_size)
{
    const float*        x0     = (const float*)d_in[0];
    const float*        y0     = (const float*)d_in[1];
    const float2*       tables = (const float2*)d_in[2];
    const unsigned int* seeds  = (const unsigned int*)d_in[3];
    const float*        levelN = (const float*)d_in[4];
    const int*          tile   = (const int*)d_in[6];   // complete_tile_size scalar
    float*              out    = (float*)d_out;

    const int B = in_sizes[0];
    const int L = in_sizes[3];
    const unsigned int T = (unsigned int)(in_sizes[2] / 2);   // FEAT_DIM = 2

    const long long hw = (long long)out_size / ((long long)B * 2LL * (long long)L);
    int H = (int)(sqrt((double)hw) + 0.5);

    const bool pow2 = (T & (T - 1)) == 0;
    const unsigned int mask = T - 1;
    const int HW = H * H;

    if (pow2 && L == 16 && (H % 2) == 0 && ((HW / 2) % 128) == 0 && B <= 65535) {
        dim3 grid((HW / 2) / 128, B);
        hashenc_vp<<<grid, 128>>>(x0, y0, tables, seeds, levelN, tile,
                                  out, H, mask);
        return;
    }

    const long long total = (long long)B * HW;
    const int threads = 256;
    const int blocks = (int)((total + threads - 1) / threads);

    if (L == 16) {
        if (pow2)
            hashenc_kernel<16, true><<<blocks, threads>>>(x0, y0, tables, seeds, levelN,
                                                          tile, out, B, H, L, T, mask);
        else
            hashenc_kernel<16, false><<<blocks, threads>>>(x0, y0, tables, seeds, levelN,
                                                           tile, out, B, H, L, T, mask);
    } else {
        if (pow2)
            hashenc_kernel<0, true><<<blocks, threads>>>(x0, y0, tables, seeds, levelN,
                                                         tile, out, B, H, L, T, mask);
        else
            hashenc_kernel<0, false><<<blocks, threads>>>(x0, y0, tables, seeds, levelN,
                                                          tile, out, B, H, L, T, mask);
    }
}

// round 17
// speedup vs baseline: 1.2142x; 1.0402x over previous
#include <cuda_runtime.h>
#include <math.h>

// LIANetLight hash-grid encoder.
// Inputs (metadata order):
//  0: x0      float32 [B]
//  1: y0      float32 [B]
//  2: tables  float32 [T, 2]
//  3: seeds   uint32  [L]
//  4: level_N float32 [L]
//  5: memorized_crop_size (scalar)
//  6: complete_tile_size  (scalar)
// Output: float32 [B, L*2, H, W]

#define HASH_P1 2654435761u
#define HASH_P2 805459861u

__device__ __forceinline__ float read_scalar_as_float(const int* p) {
    int v = *p;
    if (v > 0 && v < (1 << 24)) return (float)v;
    return __int_as_float(v);
}

__device__ __forceinline__ void store_cs(float* p, float v) {
    asm volatile("st.global.cs.f32 [%0], %1;" :: "l"(p), "f"(v) : "memory");
}

__device__ __forceinline__ void interp_store(float fx, float gx, float fy,
                                             float2 b0, float2 b1,
                                             float2 t0, float2 t1,
                                             float* pex, float* pey)
{
    const float gy = 1.0f - fy;
    const float w00 = gx * gy, w10 = fx * gy;
    const float w01 = gx * fy, w11 = fx * fy;
    const float ex = w00 * b0.x + w10 * b1.x + w01 * t0.x + w11 * t1.x;
    const float ey = w00 * b0.y + w10 * b1.y + w01 * t0.y + w11 * t1.y;
    store_cs(pex, ex);
    store_cs(pey, ey);
}

// ---------------------------------------------------------------------------
// Vertical-quad kernel: each thread handles pixels (4h'+p, w), p=0..3.
// Per level (uniform branches, thresholds with float-safety margin):
//   sc<=0.32: 4 pixels span <=3 consecutive cell rows -> 6 gathers
//   sc<=0.65: <=4 consecutive rows                    -> 8 gathers
//   sc<=0.98: two vertical pairs, 3 rows each         -> 12 gathers
//   else:     two independent pairs, 8 gathers each   -> 16 gathers
// Row selects are exact by floor monotonicity; all math matches reference.
// Warp = 32 consecutive w -> all stores coalesced. No barriers.
// Requires: T power of two, L == 16, H % 4 == 0, (H*H/4) % 128 == 0.
// ---------------------------------------------------------------------------
__global__ void __launch_bounds__(128)
hashenc_vq(const float* __restrict__ x0,
           const float* __restrict__ y0,
           const float2* __restrict__ tables,
           const unsigned int* __restrict__ seeds,
           const float* __restrict__ levelN,
           const int* __restrict__ tile_ptr,
           float* __restrict__ out,
           int H, unsigned int mask)
{
    const int L = 16;

    __shared__ float s_scale[16];
    __shared__ unsigned int s_seed[16];
    if (threadIdx.x < L) {
        const float tf = read_scalar_as_float(tile_ptr);
        s_scale[threadIdx.x] = levelN[threadIdx.x] / tf;
        s_seed[threadIdx.x]  = seeds[threadIdx.x];
    }
    __syncthreads();

    const int HW  = H * H;
    const int b   = blockIdx.y;
    const int idx = (int)(blockIdx.x * 128u + threadIdx.x);  // < H/4*H by grid
    const int hh  = idx / H;          // 0..H/4-1
    const int w   = idx - hh * H;     // 0..H-1
    const int h1  = 4 * hh;

    const float ox = __ldg(&x0[b]);
    const float oy = __ldg(&y0[b]);
    const float px  = (float)w + ox;
    const float py0 = (float)h1 + oy;

    float* outb = out + (size_t)b * (size_t)(2 * L) * (size_t)HW
                      + (size_t)h1 * (size_t)H + w;     // pixel0; pixel p = +p*H

    #pragma unroll
    for (int l = 0; l < L; l++) {
        const float sc        = s_scale[l];
        const unsigned int se = s_seed[l];

        // shared x-chain
        const float xn  = px * sc;
        const float fxf = floorf(xn);
        const float fx  = xn - fxf;
        const float gx  = 1.0f - fx;
        const unsigned int hx0 = (unsigned int)(int)fxf * HASH_P1;
        const unsigned int hx1 = hx0 + HASH_P1;

        // per-pixel y chains (py_p = py0 + p, exact in float)
        float fy[4]; int iy[4];
        #pragma unroll
        for (int p = 0; p < 4; p++) {
            const float yn  = (py0 + (float)p) * sc;
            const float fyf = floorf(yn);
            fy[p] = yn - fyf;
            iy[p] = (int)fyf;
        }

        float* oex = outb + (size_t)(2 * l)     * (size_t)HW;
        float* oey = outb + (size_t)(2 * l + 1) * (size_t)HW;

        if (sc <= 0.32f) {
            // 3 consecutive rows iyA..iyA+2; k_p = iy_p - iyA in {0,1}
            const int iyA = iy[0];
            unsigned int hA = (unsigned int)iyA * HASH_P2;
            unsigned int hB = hA + HASH_P2;
            unsigned int hC = hB + HASH_P2;
            hA ^= se; hB ^= se; hC ^= se;
            const float2 A0 = __ldg(&tables[(hx0 ^ hA) & mask]);
            const float2 A1 = __ldg(&tables[(hx1 ^ hA) & mask]);
            const float2 B0 = __ldg(&tables[(hx0 ^ hB) & mask]);
            const float2 B1 = __ldg(&tables[(hx1 ^ hB) & mask]);
            const float2 C0 = __ldg(&tables[(hx0 ^ hC) & mask]);
            const float2 C1 = __ldg(&tables[(hx1 ^ hC) & mask]);
            #pragma unroll
            for (int p = 0; p < 4; p++) {
                const bool k1 = (iy[p] != iyA);
                const float2 b0 = k1 ? B0 : A0;
                const float2 b1 = k1 ? B1 : A1;
                const float2 t0 = k1 ? C0 : B0;
                const float2 t1 = k1 ? C1 : B1;
                interp_store(fx, gx, fy[p], b0, b1, t0, t1, oex + p * H, oey + p * H);
            }
        } else if (sc <= 0.65f) {
            // 4 consecutive rows iyA..iyA+3; k_p in {0,1,2}
            const int iyA = iy[0];
            unsigned int hA = (unsigned int)iyA * HASH_P2;
            unsigned int hB = hA + HASH_P2;
            unsigned int hC = hB + HASH_P2;
            unsigned int hD = hC + HASH_P2;
            hA ^= se; hB ^= se; hC ^= se; hD ^= se;
            const float2 A0 = __ldg(&tables[(hx0 ^ hA) & mask]);
            const float2 A1 = __ldg(&tables[(hx1 ^ hA) & mask]);
            const float2 B0 = __ldg(&tables[(hx0 ^ hB) & mask]);
            const float2 B1 = __ldg(&tables[(hx1 ^ hB) & mask]);
            const float2 C0 = __ldg(&tables[(hx0 ^ hC) & mask]);
            const float2 C1 = __ldg(&tables[(hx1 ^ hC) & mask]);
            const float2 D0 = __ldg(&tables[(hx0 ^ hD) & mask]);
            const float2 D1 = __ldg(&tables[(hx1 ^ hD) & mask]);
            #pragma unroll
            for (int p = 0; p < 4; p++) {
                const int k = iy[p] - iyA;           // 0,1,2
                const float2 b0 = (k == 0) ? A0 : ((k == 1) ? B0 : C0);
                const float2 b1 = (k == 0) ? A1 : ((k == 1) ? B1 : C1);
                const float2 t0 = (k == 0) ? B0 : ((k == 1) ? C0 : D0);
                const float2 t1 = (k == 0) ? B1 : ((k == 1) ? C1 : D1);
                interp_store(fx, gx, fy[p], b0, b1, t0, t1, oex + p * H, oey + p * H);
            }
        } else if (sc <= 0.98f) {
            // two vertical pairs, 3 rows each
            #pragma unroll
            for (int r = 0; r < 2; r++) {
                const int pa = 2 * r, pb = 2 * r + 1;
                unsigned int hA = (unsigned int)iy[pa] * HASH_P2;
                unsigned int hB = hA + HASH_P2;
                unsigned int hC = (unsigned int)iy[pb] * HASH_P2 + HASH_P2;
                hA ^= se; hB ^= se; hC ^= se;
                const float2 A0 = __ldg(&tables[(hx0 ^ hA) & mask]);
                const float2 A1 = __ldg(&tables[(hx1 ^ hA) & mask]);
                const float2 B0 = __ldg(&tables[(hx0 ^ hB) & mask]);
                const float2 B1 = __ldg(&tables[(hx1 ^ hB) & mask]);
                const float2 C0 = __ldg(&tables[(hx0 ^ hC) & mask]);
                const float2 C1 = __ldg(&tables[(hx1 ^ hC) & mask]);
                interp_store(fx, gx, fy[pa], A0, A1, B0, B1, oex + pa * H, oey + pa * H);
                const bool same = (iy[pb] == iy[pa]);
                const float2 b0 = same ? A0 : B0;
                const float2 b1 = same ? A1 : B1;
                interp_store(fx, gx, fy[pb], b0, b1, C0, C1, oex + pb * H, oey + pb * H);
            }
        } else {
            // fine levels: two independent pairs, 8 gathers each
            #pragma unroll
            for (int r = 0; r < 2; r++) {
                const int pa = 2 * r, pb = 2 * r + 1;
                unsigned int hA = (unsigned int)iy[pa] * HASH_P2;
                unsigned int hB = hA + HASH_P2;
                unsigned int hC = (unsigned int)iy[pb] * HASH_P2;
                unsigned int hD = hC + HASH_P2;
                hA ^= se; hB ^= se; hC ^= se; hD ^= se;
                const float2 A0 = __ldg(&tables[(hx0 ^ hA) & mask]);
                const float2 A1 = __ldg(&tables[(hx1 ^ hA) & mask]);
                const float2 B0 = __ldg(&tables[(hx0 ^ hB) & mask]);
                const float2 B1 = __ldg(&tables[(hx1 ^ hB) & mask]);
                const float2 C0 = __ldg(&tables[(hx0 ^ hC) & mask]);
                const float2 C1 = __ldg(&tables[(hx1 ^ hC) & mask]);
                const float2 D0 = __ldg(&tables[(hx0 ^ hD) & mask]);
                const float2 D1 = __ldg(&tables[(hx1 ^ hD) & mask]);
                interp_store(fx, gx, fy[pa], A0, A1, B0, B1, oex + pa * H, oey + pa * H);
                interp_store(fx, gx, fy[pb], C0, C1, D0, D1, oex + pb * H, oey + pb * H);
            }
        }
    }
}

// ---------------------------------------------------------------------------
// Generic fallback: one thread per pixel, runtime L / non-pow2 T.
// ---------------------------------------------------------------------------
template <int LFIX, bool POW2>
__global__ void __launch_bounds__(256)
hashenc_kernel(const float* __restrict__ x0,
               const float* __restrict__ y0,
               const float2* __restrict__ tables,
               const unsigned int* __restrict__ seeds,
               const float* __restrict__ levelN,
               const int* __restrict__ tile_ptr,
               float* __restrict__ out,
               int B, int H, int Lrt,
               unsigned int T, unsigned int mask)
{
    const int L = (LFIX > 0) ? LFIX : Lrt;

    __shared__ float s_scale[64];
    __shared__ unsigned int s_seed[64];
    if (threadIdx.x < L) {
        float tf = read_scalar_as_float(tile_ptr);
        s_scale[threadIdx.x] = levelN[threadIdx.x] / tf;
        s_seed[threadIdx.x]  = seeds[threadIdx.x];
    }
    __syncthreads();

    const int HW = H * H;
    const long long total = (long long)B * HW;
    const long long tid = (long long)blockIdx.x * blockDim.x + threadIdx.x;
    if (tid >= total) return;

    const int pix = (int)(tid % HW);
    const int b   = (int)(tid / HW);
    const int w   = pix % H;
    const int h   = pix / H;

    const float px = (float)w + x0[b];
    const float py = (float)h + y0[b];

    float* outb = out + (size_t)b * (size_t)(2 * L) * (size_t)HW + pix;

    #pragma unroll
    for (int l = 0; l < L; l++) {
        const float sc = s_scale[l];
        const float xn = px * sc;
        const float yn = py * sc;
        const float fx0f = floorf(xn);
        const float fy0f = floorf(yn);
        const int ix0 = (int)fx0f;
        const int iy0 = (int)fy0f;
        const float fx = xn - fx0f;
        const float fy = yn - fy0f;

        const unsigned int se  = s_seed[l];
        const unsigned int hx0 = (unsigned int)ix0 * HASH_P1;
        const unsigned int hx1 = hx0 + HASH_P1;
        const unsigned int hy0 = (unsigned int)iy0 * HASH_P2;
        const unsigned int hy1 = hy0 + HASH_P2;

        unsigned int i00, i10, i01, i11;
        if (POW2) {
            i00 = (hx0 ^ hy0 ^ se) & mask;
            i10 = (hx1 ^ hy0 ^ se) & mask;
            i01 = (hx0 ^ hy1 ^ se) & mask;
            i11 = (hx1 ^ hy1 ^ se) & mask;
        } else {
            i00 = (hx0 ^ hy0 ^ se) % T;
            i10 = (hx1 ^ hy0 ^ se) % T;
            i01 = (hx0 ^ hy1 ^ se) % T;
            i11 = (hx1 ^ hy1 ^ se) % T;
        }

        const float2 f00 = __ldg(&tables[i00]);
        const float2 f10 = __ldg(&tables[i10]);
        const float2 f01 = __ldg(&tables[i01]);
        const float2 f11 = __ldg(&tables[i11]);

        const float gx = 1.0f - fx;
        const float gy = 1.0f - fy;
        const float w00 = gx * gy;
        const float w10 = fx * gy;
        const float w01 = gx * fy;
        const float w11 = fx * fy;

        const float ex = w00 * f00.x + w10 * f10.x + w01 * f01.x + w11 * f11.x;
        const float ey = w00 * f00.y + w10 * f10.y + w01 * f01.y + w11 * f11.y;

        outb[(size_t)(2 * l)     * (size_t)HW] = ex;
        outb[(size_t)(2 * l + 1) * (size_t)HW] = ey;
    }
}

extern "C" void kernel_launch(void* const* d_in, const int* in_sizes, int n_in,
                              void* d_out, int out_size)
{
    const float*        x0     = (const float*)d_in[0];
    const float*        y0     = (const float*)d_in[1];
    const float2*       tables = (const float2*)d_in[2];
    const unsigned int* seeds  = (const unsigned int*)d_in[3];
    const float*        levelN = (const float*)d_in[4];
    const int*          tile   = (const int*)d_in[6];   // complete_tile_size scalar
    float*              out    = (float*)d_out;

    const int B = in_sizes[0];
    const int L = in_sizes[3];
    const unsigned int T = (unsigned int)(in_sizes[2] / 2);   // FEAT_DIM = 2

    const long long hw = (long long)out_size / ((long long)B * 2LL * (long long)L);
    int H = (int)(sqrt((double)hw) + 0.5);

    const bool pow2 = (T & (T - 1)) == 0;
    const unsigned int mask = T - 1;
    const int HW = H * H;

    if (pow2 && L == 16 && (H % 4) == 0 && ((HW / 4) % 128) == 0 && B <= 65535) {
        dim3 grid((HW / 4) / 128, B);
        hashenc_vq<<<grid, 128>>>(x0, y0, tables, seeds, levelN, tile,
                                  out, H, mask);
        return;
    }

    const long long total = (long long)B * HW;
    const int threads = 256;
    const int blocks = (int)((total + threads - 1) / threads);

    if (L == 16) {
        if (pow2)
            hashenc_kernel<16, true><<<blocks, threads>>>(x0, y0, tables, seeds, levelN,
                                                          tile, out, B, H, L, T, mask);
        else
            hashenc_kernel<16, false><<<blocks, threads>>>(x0, y0, tables, seeds, levelN,
                                                           tile, out, B, H, L, T, mask);
    } else {
        if (pow2)
            hashenc_kernel<0, true><<<blocks, threads>>>(x0, y0, tables, seeds, levelN,
                                                         tile, out, B, H, L, T, mask);
        else
            hashenc_kernel<0, false><<<blocks, threads>>>(x0, y0, tables, seeds, levelN,
                                                          tile, out, B, H, L, T, mask);
    }
}